// round 14
// baseline (speedup 1.0000x reference)
#include <cuda_runtime.h>
#include <cuda_bf16.h>
#include <cstdint>

#define HID 90
#define HP 96
#define NNODES 1024
#define BATCH 1024
#define TPB 256
#define ROWS 128
#define RS 400               // B tile row stride (bytes) — conflict-free ldmatrix
#define ES2 48               // E / W1B row stride (bytes, k=8+pad) — conflict-free

// ---------------- device globals (no allocation allowed) ----------------
__device__ __align__(16) float Bimg[96 * 100];       // W2^T, tf32, k-permuted
__device__ __align__(16) float W1Bimg[96 * 12];      // [W1 | b1], logical order, k8

// ---------------- smem layout ----------------
#define SM_B    0            // 96 x 400 = 38400
#define SM_W1B  38400        // 96 x 48  = 4608  -> 43008
#define SM_E    43008        // 128 x 48 = 6144  -> 49152
#define SM_BW   49152        // 96 (b2,W3) pairs = 768
#define SM_TOTAL 49920

__device__ __forceinline__ uint32_t smem_u32(const void* p) {
    uint32_t a;
    asm("{ .reg .u64 t; cvta.to.shared.u64 t, %1; cvt.u32.u64 %0, t; }"
        : "=r"(a) : "l"(p));
    return a;
}
__device__ __forceinline__ void ldsm_x4(uint32_t& r0, uint32_t& r1,
                                        uint32_t& r2, uint32_t& r3, uint32_t a) {
    asm volatile("ldmatrix.sync.aligned.m8n8.x4.shared.b16 {%0,%1,%2,%3}, [%4];"
                 : "=r"(r0), "=r"(r1), "=r"(r2), "=r"(r3) : "r"(a));
}
__device__ __forceinline__ void mma_tf32(float* c, uint32_t a0, uint32_t a1,
                                         uint32_t a2, uint32_t a3,
                                         uint32_t b0, uint32_t b1) {
    asm volatile(
        "mma.sync.aligned.m16n8k8.row.col.f32.tf32.tf32.f32 "
        "{%0,%1,%2,%3}, {%4,%5,%6,%7}, {%8,%9}, {%0,%1,%2,%3};"
        : "+f"(c[0]), "+f"(c[1]), "+f"(c[2]), "+f"(c[3])
        : "r"(a0), "r"(a1), "r"(a2), "r"(a3), "r"(b0), "r"(b1));
}
__device__ __forceinline__ void mma_tf32f(float* c, const float* a,
                                          uint32_t b0, uint32_t b1) {
    mma_tf32(c, __float_as_uint(a[0]), __float_as_uint(a[1]),
                __float_as_uint(a[2]), __float_as_uint(a[3]), b0, b1);
}
__device__ __forceinline__ uint32_t to_tf32(float x) {
    uint32_t r;
    asm("cvt.rna.tf32.f32 %0, %1;" : "=r"(r) : "r"(__float_as_uint(x)));
    return r;
}
__device__ __forceinline__ float elu(float v) {
    return v > 0.f ? v : (__expf(v) - 1.f);
}

// ---------------- prep kernel ----------------
// Bimg k-dim: logical h1 unit c stored at physical sigma(c)=(c&1)*4+(c>>1)
// within each 8-block. W1B stays in logical order, k8 = [W1 rows 0-6 | b1].
__global__ void prep_kernel(const float* __restrict__ W1,
                            const float* __restrict__ b1,
                            const float* __restrict__ W2) {
    int c = blockIdx.x;       // 0..95 logical h1 unit
    int j = threadIdx.x;      // 0..127
    int p = (c & ~7) | (((c & 1) << 2) | ((c & 7) >> 1));
    if (j < 96) {
        float w = (c < HID && j < HID) ? W2[c * HID + j] : 0.f;
        Bimg[j * 100 + p] = __uint_as_float(to_tf32(w));
    }
    if (j < 12) {
        float v = 0.f;
        if (c < HID) {
            if (j < 7)       v = W1[j * HID + c];
            else if (j == 7) v = b1[c];
        }
        W1Bimg[c * 12 + j] = __uint_as_float(to_tf32(v));
    }
}

// ---------------- main kernel: fused 3-layer MLP, 2 images per CTA ------
__global__ void __launch_bounds__(TPB, 4)
lrf_main_kernel(const float* __restrict__ x,
                const float* __restrict__ controls,
                const float* __restrict__ b2,
                const float* __restrict__ W3,
                const float* __restrict__ b3,
                const int* __restrict__ inputs_list,
                const int* __restrict__ control_list,
                float* __restrict__ out) {
    extern __shared__ char sm[];
    const uint32_t smb = smem_u32(sm);
    const int tid = threadIdx.x;
    const int wid = tid >> 5, lid = tid & 31;
    const int bpair = (blockIdx.x >> 3) * 2;
    const int n0 = (blockIdx.x & 7) * ROWS;
    const int g = lid >> 2, q = lid & 3;

    // ---- one-time staging ----
    {
        const uint4* src = (const uint4*)Bimg;
        uint4* dst = (uint4*)(sm + SM_B);
        for (int i = tid; i < 38400 / 16; i += TPB) dst[i] = src[i];
        for (int i = tid; i < 96 * 12 / 4; i += TPB)
            ((float4*)(sm + SM_W1B))[i] = ((const float4*)W1Bimg)[i];
    }
    if (tid >= 128 && tid < 128 + HP) {
        int c = tid - 128;
        float bb = (c < HID) ? b2[c] : 0.f;
        float ww = (c < HID) ? W3[c] : 0.f;
        ((float*)(sm + SM_BW))[c * 2]     = bb;
        ((float*)(sm + SM_BW))[c * 2 + 1] = ww;
    }

    // ldmatrix addresses (b-invariant)
    const uint32_t eAddr = smb + SM_E
        + (uint32_t)(wid * 16 + (lid & 7) + ((lid >> 3) & 1) * 8) * ES2
        + (uint32_t)(lid >> 4) * 16;
    const uint32_t wAddr = smb + SM_W1B
        + (uint32_t)((lid & 7) + (lid >> 4) * 8) * ES2
        + (uint32_t)((lid >> 3) & 1) * 16;
    const uint32_t bB = smb + SM_B
        + (uint32_t)(lid & 7) * RS + (uint32_t)(lid >> 3) * 16;

    for (int r2 = 0; r2 < 2; r2++) {
        const int b = bpair + r2;
        __syncthreads();   // staging done / prior image's E reads done

        // ---- build E: [128 x 8] rna-rounded electrode vectors + bias col ----
        if (tid < ROWS) {
            int n = n0 + tid;
            int pw = n & 31, ph = n >> 5;
            const float* xb = x + (size_t)b * 4096 + ph * 128 + pw * 2;
            float2 r0v = *reinterpret_cast<const float2*>(xb);
            float2 r1v = *reinterpret_cast<const float2*>(xb + 64);
            int4 il = *reinterpret_cast<const int4*>(inputs_list + n * 4);
            int cl0 = control_list[n * 3], cl1 = control_list[n * 3 + 1],
                cl2 = control_list[n * 3 + 2];
            float cv0 = controls[n * 3], cv1 = controls[n * 3 + 1],
                  cv2 = controls[n * 3 + 2];
            float* er = (float*)(sm + SM_E + tid * ES2);
            float4 z = make_float4(0.f, 0.f, 0.f, 0.f);
            ((float4*)er)[0] = z; ((float4*)er)[1] = z; ((float4*)er)[2] = z;
            er[il.x] = __uint_as_float(to_tf32(r0v.x));
            er[il.y] = __uint_as_float(to_tf32(r0v.y));
            er[il.z] = __uint_as_float(to_tf32(r1v.x));
            er[il.w] = __uint_as_float(to_tf32(r1v.y));
            er[cl0]  = __uint_as_float(to_tf32(cv0));
            er[cl1]  = __uint_as_float(to_tf32(cv1));
            er[cl2]  = __uint_as_float(to_tf32(cv2));
            er[7] = 1.0f;
        }
        __syncthreads();

        // ---- phase 1: h1 = elu(E·W1B), single k8 pass; C frags become
        //      phase-2 A frags (Bimg k-permutation makes layouts meet) ----
        float aF[12][4];
        {
            float acc1[12][4];
#pragma unroll
            for (int nt = 0; nt < 12; nt++)
#pragma unroll
                for (int c = 0; c < 4; c++) acc1[nt][c] = 0.f;

            uint32_t a0, a1, a2, a3;
            ldsm_x4(a0, a1, a2, a3, eAddr);
#pragma unroll
            for (int nt2 = 0; nt2 < 6; nt2++) {
                uint32_t b0, b1, b2r, b3r;
                ldsm_x4(b0, b1, b2r, b3r, wAddr + (uint32_t)nt2 * 16 * ES2);
                mma_tf32(acc1[2 * nt2],     a0, a1, a2, a3, b0,  b1);
                mma_tf32(acc1[2 * nt2 + 1], a0, a1, a2, a3, b2r, b3r);
            }
            // elu + C->A component reorder {c0,c2,c1,c3}
#pragma unroll
            for (int nt = 0; nt < 12; nt++) {
                aF[nt][0] = elu(acc1[nt][0]);
                aF[nt][1] = elu(acc1[nt][2]);
                aF[nt][2] = elu(acc1[nt][1]);
                aF[nt][3] = elu(acc1[nt][3]);
            }
        }

        // ---- phase 2+3: nt-outer (12 n8 tiles), acc consumed immediately
        //      by the elu+W3 epilogue — minimal live registers ----
        float p0 = 0.f, p1 = 0.f;
        const char* bwbase = sm + SM_BW + (size_t)q * 16;
#pragma unroll
        for (int nt = 0; nt < 12; nt++) {
            float acc[4];
            acc[0] = acc[1] = acc[2] = acc[3] = 0.f;
            const uint32_t bRow = bB + (uint32_t)nt * 8 * RS;
#pragma unroll
            for (int kh = 0; kh < 6; kh++) {
                uint32_t b0, b1, b2r, b3r;
                ldsm_x4(b0, b1, b2r, b3r, bRow + kh * 64);
                mma_tf32f(acc, aF[2 * kh],     b0,  b1);
                mma_tf32f(acc, aF[2 * kh + 1], b2r, b3r);
            }
            float4 bw = *reinterpret_cast<const float4*>(bwbase + nt * 64);
            p0 = fmaf(elu(acc[0] + bw.x), bw.y, p0);
            p0 = fmaf(elu(acc[1] + bw.z), bw.w, p0);
            p1 = fmaf(elu(acc[2] + bw.x), bw.y, p1);
            p1 = fmaf(elu(acc[3] + bw.z), bw.w, p1);
        }
        p0 += __shfl_xor_sync(0xffffffffu, p0, 1);
        p0 += __shfl_xor_sync(0xffffffffu, p0, 2);
        p1 += __shfl_xor_sync(0xffffffffu, p1, 1);
        p1 += __shfl_xor_sync(0xffffffffu, p1, 2);
        if (q == 0) {
            float b3v = b3[0];
            int r = n0 + wid * 16 + g;
            out[(size_t)b * NNODES + r]     = p0 + b3v;
            out[(size_t)b * NNODES + r + 8] = p1 + b3v;
        }
    }
}

extern "C" void kernel_launch(void* const* d_in, const int* in_sizes, int n_in,
                              void* d_out, int out_size) {
    const float* x            = (const float*)d_in[0];
    const float* controls     = (const float*)d_in[1];
    const float* W1           = (const float*)d_in[2];
    const float* b1           = (const float*)d_in[3];
    const float* W2           = (const float*)d_in[4];
    const float* b2           = (const float*)d_in[5];
    const float* W3           = (const float*)d_in[6];
    const float* b3           = (const float*)d_in[7];
    const int*   inputs_list  = (const int*)d_in[8];
    const int*   control_list = (const int*)d_in[9];
    float* out = (float*)d_out;

    cudaFuncSetAttribute(lrf_main_kernel,
                         cudaFuncAttributeMaxDynamicSharedMemorySize, SM_TOTAL);

    prep_kernel<<<96, 128>>>(W1, b1, W2);
    lrf_main_kernel<<<(BATCH / 2) * (NNODES / ROWS), TPB, SM_TOTAL>>>(
        x, controls, b2, W3, b3, inputs_list, control_list, out);
}

// round 15
// speedup vs baseline: 1.1730x; 1.1730x over previous
#include <cuda_runtime.h>
#include <cuda_bf16.h>
#include <cstdint>

#define HID 90
#define HP 96
#define NNODES 1024
#define BATCH 1024
#define TPB 256
#define ROWS 128
#define RS 400               // B tile row stride (bytes) — conflict-free ldmatrix
#define ES2 48               // E / W1B row stride (bytes, k=8+pad) — conflict-free

// ---------------- device globals (no allocation allowed) ----------------
__device__ __align__(16) float Bimg[96 * 100];       // W2^T, tf32, k-permuted
__device__ __align__(16) float W1Bimg[96 * 12];      // [W1 | b1], logical order, k8

// ---------------- smem layout ----------------
#define SM_B    0            // 96 x 400 = 38400
#define SM_W1B  38400        // 96 x 48  = 4608  -> 43008
#define SM_E    43008        // 128 x 48 = 6144  -> 49152
#define SM_BW   49152        // 96 (b2,W3) pairs = 768
#define SM_TOTAL 49920

__device__ __forceinline__ uint32_t smem_u32(const void* p) {
    uint32_t a;
    asm("{ .reg .u64 t; cvta.to.shared.u64 t, %1; cvt.u32.u64 %0, t; }"
        : "=r"(a) : "l"(p));
    return a;
}
__device__ __forceinline__ void ldsm_x4(uint32_t& r0, uint32_t& r1,
                                        uint32_t& r2, uint32_t& r3, uint32_t a) {
    asm volatile("ldmatrix.sync.aligned.m8n8.x4.shared.b16 {%0,%1,%2,%3}, [%4];"
                 : "=r"(r0), "=r"(r1), "=r"(r2), "=r"(r3) : "r"(a));
}
__device__ __forceinline__ void mma_tf32(float* c, uint32_t a0, uint32_t a1,
                                         uint32_t a2, uint32_t a3,
                                         uint32_t b0, uint32_t b1) {
    asm volatile(
        "mma.sync.aligned.m16n8k8.row.col.f32.tf32.tf32.f32 "
        "{%0,%1,%2,%3}, {%4,%5,%6,%7}, {%8,%9}, {%0,%1,%2,%3};"
        : "+f"(c[0]), "+f"(c[1]), "+f"(c[2]), "+f"(c[3])
        : "r"(a0), "r"(a1), "r"(a2), "r"(a3), "r"(b0), "r"(b1));
}
__device__ __forceinline__ void mma_tf32f(float* c, const float* a,
                                          uint32_t b0, uint32_t b1) {
    mma_tf32(c, __float_as_uint(a[0]), __float_as_uint(a[1]),
                __float_as_uint(a[2]), __float_as_uint(a[3]), b0, b1);
}
__device__ __forceinline__ uint32_t to_tf32(float x) {
    uint32_t r;
    asm("cvt.rna.tf32.f32 %0, %1;" : "=r"(r) : "r"(__float_as_uint(x)));
    return r;
}
// Branchless ELU: exact for all v.
//   v <= 0: fmax=0, exp(v)-1  (identical to reference path)
//   v >  0: fmax=v, exp(0)-1 = 0 exactly
__device__ __forceinline__ float elu(float v) {
    return fmaxf(v, 0.f) + (__expf(fminf(v, 0.f)) - 1.f);
}

// ---------------- prep kernel ----------------
// Bimg k-dim: logical h1 unit c stored at physical sigma(c)=(c&1)*4+(c>>1)
// within each 8-block. W1B stays in logical order, k8 = [W1 rows 0-6 | b1].
__global__ void prep_kernel(const float* __restrict__ W1,
                            const float* __restrict__ b1,
                            const float* __restrict__ W2) {
    int c = blockIdx.x;       // 0..95 logical h1 unit
    int j = threadIdx.x;      // 0..127
    int p = (c & ~7) | (((c & 1) << 2) | ((c & 7) >> 1));
    if (j < 96) {
        float w = (c < HID && j < HID) ? W2[c * HID + j] : 0.f;
        Bimg[j * 100 + p] = __uint_as_float(to_tf32(w));
    }
    if (j < 12) {
        float v = 0.f;
        if (c < HID) {
            if (j < 7)       v = W1[j * HID + c];
            else if (j == 7) v = b1[c];
        }
        W1Bimg[c * 12 + j] = __uint_as_float(to_tf32(v));
    }
}

// ---------------- main kernel: fused 3-layer MLP, 2 images per CTA ------
__global__ void __launch_bounds__(TPB, 3)
lrf_main_kernel(const float* __restrict__ x,
                const float* __restrict__ controls,
                const float* __restrict__ b2,
                const float* __restrict__ W3,
                const float* __restrict__ b3,
                const int* __restrict__ inputs_list,
                const int* __restrict__ control_list,
                float* __restrict__ out) {
    extern __shared__ char sm[];
    const uint32_t smb = smem_u32(sm);
    const int tid = threadIdx.x;
    const int wid = tid >> 5, lid = tid & 31;
    const int bpair = (blockIdx.x >> 3) * 2;
    const int n0 = (blockIdx.x & 7) * ROWS;
    const int g = lid >> 2, q = lid & 3;

    // ---- one-time staging ----
    {
        const uint4* src = (const uint4*)Bimg;
        uint4* dst = (uint4*)(sm + SM_B);
        for (int i = tid; i < 38400 / 16; i += TPB) dst[i] = src[i];
        for (int i = tid; i < 96 * 12 / 4; i += TPB)
            ((float4*)(sm + SM_W1B))[i] = ((const float4*)W1Bimg)[i];
    }
    if (tid >= 128 && tid < 128 + HP) {
        int c = tid - 128;
        float bb = (c < HID) ? b2[c] : 0.f;
        float ww = (c < HID) ? W3[c] : 0.f;
        ((float*)(sm + SM_BW))[c * 2]     = bb;
        ((float*)(sm + SM_BW))[c * 2 + 1] = ww;
    }

    // ldmatrix addresses (b-invariant)
    const uint32_t eAddr = smb + SM_E
        + (uint32_t)(wid * 16 + (lid & 7) + ((lid >> 3) & 1) * 8) * ES2
        + (uint32_t)(lid >> 4) * 16;
    const uint32_t wAddr = smb + SM_W1B
        + (uint32_t)((lid & 7) + (lid >> 4) * 8) * ES2
        + (uint32_t)((lid >> 3) & 1) * 16;
    const uint32_t bB = smb + SM_B
        + (uint32_t)(lid & 7) * RS + (uint32_t)(lid >> 3) * 16;

    for (int r2 = 0; r2 < 2; r2++) {
        const int b = bpair + r2;
        __syncthreads();   // staging done / prior image's E reads done

        // ---- build E: [128 x 8] rna-rounded electrode vectors + bias col ----
        if (tid < ROWS) {
            int n = n0 + tid;
            int pw = n & 31, ph = n >> 5;
            const float* xb = x + (size_t)b * 4096 + ph * 128 + pw * 2;
            float2 r0v = *reinterpret_cast<const float2*>(xb);
            float2 r1v = *reinterpret_cast<const float2*>(xb + 64);
            int4 il = *reinterpret_cast<const int4*>(inputs_list + n * 4);
            int cl0 = control_list[n * 3], cl1 = control_list[n * 3 + 1],
                cl2 = control_list[n * 3 + 2];
            float cv0 = controls[n * 3], cv1 = controls[n * 3 + 1],
                  cv2 = controls[n * 3 + 2];
            float* er = (float*)(sm + SM_E + tid * ES2);
            float4 z = make_float4(0.f, 0.f, 0.f, 0.f);
            ((float4*)er)[0] = z; ((float4*)er)[1] = z; ((float4*)er)[2] = z;
            er[il.x] = __uint_as_float(to_tf32(r0v.x));
            er[il.y] = __uint_as_float(to_tf32(r0v.y));
            er[il.z] = __uint_as_float(to_tf32(r1v.x));
            er[il.w] = __uint_as_float(to_tf32(r1v.y));
            er[cl0]  = __uint_as_float(to_tf32(cv0));
            er[cl1]  = __uint_as_float(to_tf32(cv1));
            er[cl2]  = __uint_as_float(to_tf32(cv2));
            er[7] = 1.0f;
        }
        __syncthreads();

        // ---- phase 1: h1 = elu(E·W1B), single k8 pass; C frags become
        //      phase-2 A frags (Bimg k-permutation makes layouts meet) ----
        float aF[12][4];
        {
            float acc1[12][4];
#pragma unroll
            for (int nt = 0; nt < 12; nt++)
#pragma unroll
                for (int c = 0; c < 4; c++) acc1[nt][c] = 0.f;

            uint32_t a0, a1, a2, a3;
            ldsm_x4(a0, a1, a2, a3, eAddr);
#pragma unroll
            for (int nt2 = 0; nt2 < 6; nt2++) {
                uint32_t b0, b1, b2r, b3r;
                ldsm_x4(b0, b1, b2r, b3r, wAddr + (uint32_t)nt2 * 16 * ES2);
                mma_tf32(acc1[2 * nt2],     a0, a1, a2, a3, b0,  b1);
                mma_tf32(acc1[2 * nt2 + 1], a0, a1, a2, a3, b2r, b3r);
            }
            // elu + C->A component reorder {c0,c2,c1,c3}
#pragma unroll
            for (int nt = 0; nt < 12; nt++) {
                aF[nt][0] = elu(acc1[nt][0]);
                aF[nt][1] = elu(acc1[nt][2]);
                aF[nt][2] = elu(acc1[nt][1]);
                aF[nt][3] = elu(acc1[nt][3]);
            }
        }

        // ---- phase 2+3: warp = m16 x n96 in two n48 halves, A in regs ----
        float p0 = 0.f, p1 = 0.f;
        const char* bwbase = sm + SM_BW + (size_t)q * 16;
#pragma unroll
        for (int h = 0; h < 2; h++) {
            float acc[6][4];
#pragma unroll
            for (int nt = 0; nt < 6; nt++)
#pragma unroll
                for (int c = 0; c < 4; c++) acc[nt][c] = 0.f;

            const uint32_t bRow = bB + (uint32_t)h * 48 * RS;
#pragma unroll
            for (int kh = 0; kh < 6; kh++) {
#pragma unroll
                for (int nt = 0; nt < 6; nt++) {
                    uint32_t b0, b1, b2r, b3r;
                    ldsm_x4(b0, b1, b2r, b3r,
                            bRow + (uint32_t)nt * 8 * RS + kh * 64);
                    mma_tf32f(acc[nt], aF[2 * kh],     b0,  b1);
                    mma_tf32f(acc[nt], aF[2 * kh + 1], b2r, b3r);
                }
            }
#pragma unroll
            for (int nt = 0; nt < 6; nt++) {
                float4 bw = *reinterpret_cast<const float4*>(
                    bwbase + h * 384 + nt * 64);
                p0 = fmaf(elu(acc[nt][0] + bw.x), bw.y, p0);
                p0 = fmaf(elu(acc[nt][1] + bw.z), bw.w, p0);
                p1 = fmaf(elu(acc[nt][2] + bw.x), bw.y, p1);
                p1 = fmaf(elu(acc[nt][3] + bw.z), bw.w, p1);
            }
        }
        p0 += __shfl_xor_sync(0xffffffffu, p0, 1);
        p0 += __shfl_xor_sync(0xffffffffu, p0, 2);
        p1 += __shfl_xor_sync(0xffffffffu, p1, 1);
        p1 += __shfl_xor_sync(0xffffffffu, p1, 2);
        if (q == 0) {
            float b3v = b3[0];
            int r = n0 + wid * 16 + g;
            out[(size_t)b * NNODES + r]     = p0 + b3v;
            out[(size_t)b * NNODES + r + 8] = p1 + b3v;
        }
    }
}

extern "C" void kernel_launch(void* const* d_in, const int* in_sizes, int n_in,
                              void* d_out, int out_size) {
    const float* x            = (const float*)d_in[0];
    const float* controls     = (const float*)d_in[1];
    const float* W1           = (const float*)d_in[2];
    const float* b1           = (const float*)d_in[3];
    const float* W2           = (const float*)d_in[4];
    const float* b2           = (const float*)d_in[5];
    const float* W3           = (const float*)d_in[6];
    const float* b3           = (const float*)d_in[7];
    const int*   inputs_list  = (const int*)d_in[8];
    const int*   control_list = (const int*)d_in[9];
    float* out = (float*)d_out;

    cudaFuncSetAttribute(lrf_main_kernel,
                         cudaFuncAttributeMaxDynamicSharedMemorySize, SM_TOTAL);

    prep_kernel<<<96, 128>>>(W1, b1, W2);
    lrf_main_kernel<<<(BATCH / 2) * (NNODES / ROWS), TPB, SM_TOTAL>>>(
        x, controls, b2, W3, b3, inputs_list, control_list, out);
}

// round 16
// speedup vs baseline: 1.2921x; 1.1015x over previous
#include <cuda_runtime.h>
#include <cuda_bf16.h>
#include <cstdint>

#define HID 90
#define HP 96
#define NNODES 1024
#define BATCH 1024
#define TPB 256
#define ROWS 128
#define RS 400               // B tile row stride (bytes) — conflict-free ldmatrix
#define ES2 48               // E / W1B row stride (bytes, k=8+pad) — conflict-free

// ---------------- device globals (no allocation allowed) ----------------
__device__ __align__(16) float Bimg[96 * 100];       // W2^T, tf32, k-permuted
__device__ __align__(16) float W1Bimg[96 * 12];      // [W1 | b1], logical order, k8

// ---------------- smem layout ----------------
#define SM_B    0            // 96 x 400 = 38400
#define SM_W1B  38400        // 96 x 48  = 4608  -> 43008
#define SM_E0   43008        // 128 x 48 = 6144  -> 49152
#define SM_E1   49152        // 128 x 48 = 6144  -> 55296
#define SM_BW   55296        // 96 (b2,W3) pairs = 768
#define SM_TOTAL 56064

__device__ __forceinline__ uint32_t smem_u32(const void* p) {
    uint32_t a;
    asm("{ .reg .u64 t; cvta.to.shared.u64 t, %1; cvt.u32.u64 %0, t; }"
        : "=r"(a) : "l"(p));
    return a;
}
__device__ __forceinline__ void ldsm_x4(uint32_t& r0, uint32_t& r1,
                                        uint32_t& r2, uint32_t& r3, uint32_t a) {
    asm volatile("ldmatrix.sync.aligned.m8n8.x4.shared.b16 {%0,%1,%2,%3}, [%4];"
                 : "=r"(r0), "=r"(r1), "=r"(r2), "=r"(r3) : "r"(a));
}
__device__ __forceinline__ void mma_tf32(float* c, uint32_t a0, uint32_t a1,
                                         uint32_t a2, uint32_t a3,
                                         uint32_t b0, uint32_t b1) {
    asm volatile(
        "mma.sync.aligned.m16n8k8.row.col.f32.tf32.tf32.f32 "
        "{%0,%1,%2,%3}, {%4,%5,%6,%7}, {%8,%9}, {%0,%1,%2,%3};"
        : "+f"(c[0]), "+f"(c[1]), "+f"(c[2]), "+f"(c[3])
        : "r"(a0), "r"(a1), "r"(a2), "r"(a3), "r"(b0), "r"(b1));
}
__device__ __forceinline__ void mma_tf32f(float* c, const float* a,
                                          uint32_t b0, uint32_t b1) {
    mma_tf32(c, __float_as_uint(a[0]), __float_as_uint(a[1]),
                __float_as_uint(a[2]), __float_as_uint(a[3]), b0, b1);
}
__device__ __forceinline__ uint32_t to_tf32(float x) {
    uint32_t r;
    asm("cvt.rna.tf32.f32 %0, %1;" : "=r"(r) : "r"(__float_as_uint(x)));
    return r;
}
// Branchless ELU: exact for all v (v>0: exp(0)-1 = 0 exactly).
__device__ __forceinline__ float elu(float v) {
    return fmaxf(v, 0.f) + (__expf(fminf(v, 0.f)) - 1.f);
}

// ---------------- prep kernel ----------------
// Bimg k-dim: logical h1 unit c stored at physical sigma(c)=(c&1)*4+(c>>1)
// within each 8-block. W1B stays in logical order, k8 = [W1 rows 0-6 | b1].
__global__ void prep_kernel(const float* __restrict__ W1,
                            const float* __restrict__ b1,
                            const float* __restrict__ W2) {
    int c = blockIdx.x;       // 0..95 logical h1 unit
    int j = threadIdx.x;      // 0..127
    int p = (c & ~7) | (((c & 1) << 2) | ((c & 7) >> 1));
    if (j < 96) {
        float w = (c < HID && j < HID) ? W2[c * HID + j] : 0.f;
        Bimg[j * 100 + p] = __uint_as_float(to_tf32(w));
    }
    if (j < 12) {
        float v = 0.f;
        if (c < HID) {
            if (j < 7)       v = W1[j * HID + c];
            else if (j == 7) v = b1[c];
        }
        W1Bimg[c * 12 + j] = __uint_as_float(to_tf32(v));
    }
}

// ---------------- main kernel: fused 3-layer MLP, 2 images per CTA,
//                  phase-2 B fragments shared across both images ---------
__global__ void __launch_bounds__(TPB, 2)
lrf_main_kernel(const float* __restrict__ x,
                const float* __restrict__ controls,
                const float* __restrict__ b2,
                const float* __restrict__ W3,
                const float* __restrict__ b3,
                const int* __restrict__ inputs_list,
                const int* __restrict__ control_list,
                float* __restrict__ out) {
    extern __shared__ char sm[];
    const uint32_t smb = smem_u32(sm);
    const int tid = threadIdx.x;
    const int wid = tid >> 5, lid = tid & 31;
    const int bpair = (blockIdx.x >> 3) * 2;
    const int n0 = (blockIdx.x & 7) * ROWS;
    const int g = lid >> 2, q = lid & 3;

    // ---- one-time staging ----
    {
        const uint4* src = (const uint4*)Bimg;
        uint4* dst = (uint4*)(sm + SM_B);
        for (int i = tid; i < 38400 / 16; i += TPB) dst[i] = src[i];
        for (int i = tid; i < 96 * 12 / 4; i += TPB)
            ((float4*)(sm + SM_W1B))[i] = ((const float4*)W1Bimg)[i];
    }
    if (tid < HP) {
        float bb = (tid < HID) ? b2[tid] : 0.f;
        float ww = (tid < HID) ? W3[tid] : 0.f;
        ((float*)(sm + SM_BW))[tid * 2]     = bb;
        ((float*)(sm + SM_BW))[tid * 2 + 1] = ww;
    }

    // ---- build BOTH E buffers concurrently: tid<128 -> image0, else image1 ----
    {
        int half = tid >> 7;                   // 0 or 1
        int row  = tid & 127;
        int b = bpair + half;
        int n = n0 + row;
        int pw = n & 31, ph = n >> 5;
        const float* xb = x + (size_t)b * 4096 + ph * 128 + pw * 2;
        float2 r0v = *reinterpret_cast<const float2*>(xb);
        float2 r1v = *reinterpret_cast<const float2*>(xb + 64);
        int4 il = *reinterpret_cast<const int4*>(inputs_list + n * 4);
        int cl0 = control_list[n * 3], cl1 = control_list[n * 3 + 1],
            cl2 = control_list[n * 3 + 2];
        float cv0 = controls[n * 3], cv1 = controls[n * 3 + 1],
              cv2 = controls[n * 3 + 2];
        float* er = (float*)(sm + (half ? SM_E1 : SM_E0) + row * ES2);
        float4 z = make_float4(0.f, 0.f, 0.f, 0.f);
        ((float4*)er)[0] = z; ((float4*)er)[1] = z; ((float4*)er)[2] = z;
        er[il.x] = __uint_as_float(to_tf32(r0v.x));
        er[il.y] = __uint_as_float(to_tf32(r0v.y));
        er[il.z] = __uint_as_float(to_tf32(r1v.x));
        er[il.w] = __uint_as_float(to_tf32(r1v.y));
        er[cl0]  = __uint_as_float(to_tf32(cv0));
        er[cl1]  = __uint_as_float(to_tf32(cv1));
        er[cl2]  = __uint_as_float(to_tf32(cv2));
        er[7] = 1.0f;
    }
    __syncthreads();      // the ONLY barrier

    // ldmatrix addresses
    const uint32_t eAddr0 = smb + SM_E0
        + (uint32_t)(wid * 16 + (lid & 7) + ((lid >> 3) & 1) * 8) * ES2
        + (uint32_t)(lid >> 4) * 16;
    const uint32_t eAddr1 = eAddr0 + (SM_E1 - SM_E0);
    const uint32_t wAddr = smb + SM_W1B
        + (uint32_t)((lid & 7) + (lid >> 4) * 8) * ES2
        + (uint32_t)((lid >> 3) & 1) * 16;
    const uint32_t bB = smb + SM_B
        + (uint32_t)(lid & 7) * RS + (uint32_t)(lid >> 3) * 16;

    // ---- phase 1 (both images): h1 = elu(E·W1B); C frags -> A frags ----
    float aF0[12][4], aF1[12][4];
#pragma unroll
    for (int img = 0; img < 2; img++) {
        float acc1[12][4];
#pragma unroll
        for (int nt = 0; nt < 12; nt++)
#pragma unroll
            for (int c = 0; c < 4; c++) acc1[nt][c] = 0.f;

        uint32_t a0, a1, a2, a3;
        ldsm_x4(a0, a1, a2, a3, img ? eAddr1 : eAddr0);
#pragma unroll
        for (int nt2 = 0; nt2 < 6; nt2++) {
            uint32_t b0, b1, b2r, b3r;
            ldsm_x4(b0, b1, b2r, b3r, wAddr + (uint32_t)nt2 * 16 * ES2);
            mma_tf32(acc1[2 * nt2],     a0, a1, a2, a3, b0,  b1);
            mma_tf32(acc1[2 * nt2 + 1], a0, a1, a2, a3, b2r, b3r);
        }
        float (*aF)[4] = img ? aF1 : aF0;
#pragma unroll
        for (int nt = 0; nt < 12; nt++) {       // C->A reorder {c0,c2,c1,c3}
            aF[nt][0] = elu(acc1[nt][0]);
            aF[nt][1] = elu(acc1[nt][2]);
            aF[nt][2] = elu(acc1[nt][1]);
            aF[nt][3] = elu(acc1[nt][3]);
        }
    }

    // ---- phase 2+3: nt-outer; each B fragment feeds BOTH images ----
    float p00 = 0.f, p01 = 0.f, p10 = 0.f, p11 = 0.f;
    const char* bwbase = sm + SM_BW + (size_t)q * 16;
#pragma unroll
    for (int nt = 0; nt < 12; nt++) {
        float acc0[4] = {0.f, 0.f, 0.f, 0.f};
        float acc1[4] = {0.f, 0.f, 0.f, 0.f};
        const uint32_t bRow = bB + (uint32_t)nt * 8 * RS;
#pragma unroll
        for (int kh = 0; kh < 6; kh++) {
            uint32_t b0, b1, b2r, b3r;
            ldsm_x4(b0, b1, b2r, b3r, bRow + kh * 64);
            mma_tf32f(acc0, aF0[2 * kh],     b0,  b1);
            mma_tf32f(acc0, aF0[2 * kh + 1], b2r, b3r);
            mma_tf32f(acc1, aF1[2 * kh],     b0,  b1);
            mma_tf32f(acc1, aF1[2 * kh + 1], b2r, b3r);
        }
        float4 bw = *reinterpret_cast<const float4*>(bwbase + nt * 64);
        p00 = fmaf(elu(acc0[0] + bw.x), bw.y, p00);
        p00 = fmaf(elu(acc0[1] + bw.z), bw.w, p00);
        p01 = fmaf(elu(acc0[2] + bw.x), bw.y, p01);
        p01 = fmaf(elu(acc0[3] + bw.z), bw.w, p01);
        p10 = fmaf(elu(acc1[0] + bw.x), bw.y, p10);
        p10 = fmaf(elu(acc1[1] + bw.z), bw.w, p10);
        p11 = fmaf(elu(acc1[2] + bw.x), bw.y, p11);
        p11 = fmaf(elu(acc1[3] + bw.z), bw.w, p11);
    }
    p00 += __shfl_xor_sync(0xffffffffu, p00, 1);
    p00 += __shfl_xor_sync(0xffffffffu, p00, 2);
    p01 += __shfl_xor_sync(0xffffffffu, p01, 1);
    p01 += __shfl_xor_sync(0xffffffffu, p01, 2);
    p10 += __shfl_xor_sync(0xffffffffu, p10, 1);
    p10 += __shfl_xor_sync(0xffffffffu, p10, 2);
    p11 += __shfl_xor_sync(0xffffffffu, p11, 1);
    p11 += __shfl_xor_sync(0xffffffffu, p11, 2);
    if (q == 0) {
        float b3v = b3[0];
        int r = n0 + wid * 16 + g;
        out[(size_t)bpair * NNODES + r]           = p00 + b3v;
        out[(size_t)bpair * NNODES + r + 8]       = p01 + b3v;
        out[(size_t)(bpair + 1) * NNODES + r]     = p10 + b3v;
        out[(size_t)(bpair + 1) * NNODES + r + 8] = p11 + b3v;
    }
}

extern "C" void kernel_launch(void* const* d_in, const int* in_sizes, int n_in,
                              void* d_out, int out_size) {
    const float* x            = (const float*)d_in[0];
    const float* controls     = (const float*)d_in[1];
    const float* W1           = (const float*)d_in[2];
    const float* b1           = (const float*)d_in[3];
    const float* W2           = (const float*)d_in[4];
    const float* b2           = (const float*)d_in[5];
    const float* W3           = (const float*)d_in[6];
    const float* b3           = (const float*)d_in[7];
    const int*   inputs_list  = (const int*)d_in[8];
    const int*   control_list = (const int*)d_in[9];
    float* out = (float*)d_out;

    cudaFuncSetAttribute(lrf_main_kernel,
                         cudaFuncAttributeMaxDynamicSharedMemorySize, SM_TOTAL);

    prep_kernel<<<96, 128>>>(W1, b1, W2);
    lrf_main_kernel<<<(BATCH / 2) * (NNODES / ROWS), TPB, SM_TOTAL>>>(
        x, controls, b2, W3, b3, inputs_list, control_list, out);
}